// round 2
// baseline (speedup 1.0000x reference)
#include <cuda_runtime.h>
#include <cstdint>
#include <cstddef>

#define B_ 512
#define N_ 50
#define D_ 256
#define STEP_ 3

// shared-memory layout (float offsets)
#define SM_H      0
#define SM_HN     12800
#define SM_EM     25600
#define SM_STAR   26880
#define SM_STARN  27136
#define SM_AS     27392
#define SM_SIMB   28416
#define SM_NSB    28480
#define SM_GMF    28544
#define SM_NID    28608
#define SM_FLOATS 28672
#define SMEM_BYTES (SM_FLOATS * 4)

// global scratch for hg accumulation (sum of step embeddings)
__device__ float g_hg[(size_t)B_ * N_ * D_];

// ---------------- helpers ----------------
__device__ __forceinline__ float wsum(float v) {
#pragma unroll
    for (int o = 16; o; o >>= 1) v += __shfl_xor_sync(0xffffffffu, v, o);
    return v;
}
__device__ __forceinline__ float wmax(float v) {
#pragma unroll
    for (int o = 16; o; o >>= 1) v = fmaxf(v, __shfl_xor_sync(0xffffffffu, v, o));
    return v;
}
__device__ __forceinline__ float sgnf(float x) {
    return x > 0.f ? 1.f : (x < 0.f ? -1.f : 0.f);
}
__device__ __forceinline__ float dot4(float4 a, float4 b) {
    return a.x * b.x + a.y * b.y + a.z * b.z + a.w * b.w;
}
__device__ __forceinline__ float4 fma4(float p, float4 y, float4 a) {
    a.x = fmaf(p, y.x, a.x); a.y = fmaf(p, y.y, a.y);
    a.z = fmaf(p, y.z, a.z); a.w = fmaf(p, y.w, a.w);
    return a;
}
// packed f32x2 (FFMA2) — only reachable via PTX
__device__ __forceinline__ unsigned long long pk2(float lo, float hi) {
    unsigned long long r;
    asm("mov.b64 %0, {%1, %2};" : "=l"(r) : "f"(lo), "f"(hi));
    return r;
}
__device__ __forceinline__ void fma2(unsigned long long& d, unsigned long long a,
                                     unsigned long long b) {
    asm("fma.rn.f32x2 %0, %1, %2, %0;" : "+l"(d) : "l"(a), "l"(b));
}
__device__ __forceinline__ void up2(unsigned long long v, float& lo, float& hi) {
    asm("mov.b64 {%0, %1}, %2;" : "=f"(lo), "=f"(hi) : "l"(v));
}

// ---------------- fused kernel: one block per batch element ----------------
__global__ void __launch_bounds__(256, 2) sg_kernel(
    const int* __restrict__ inputs, const int* __restrict__ Am,
    const int* __restrict__ gmask, const float* __restrict__ noise,
    const float* __restrict__ emb,
    const float* __restrict__ a0, const float* __restrict__ a1,
    const float* __restrict__ a2, const float* __restrict__ a3,
    const float* __restrict__ Whn, const float* __restrict__ bhn,
    const float* __restrict__ Whn1, const float* __restrict__ bhn1,
    float* __restrict__ out0, float* __restrict__ ostar, float* __restrict__ out1)
{
    extern __shared__ float sm[];
    float* h     = sm + SM_H;      // [50][256] hidden
    float* hN    = sm + SM_HN;     // [50][256] scratch / h0
    float* eM    = sm + SM_EM;     // [25][50] attention half-matrix
    float* star  = sm + SM_STAR;   // [256]
    float* starN = sm + SM_STARN;  // [256]
    float* aS    = sm + SM_AS;     // [4][256] a-vectors
    float* simb  = sm + SM_SIMB;   // [64] per-row scalar
    float* nsb   = sm + SM_NSB;    // [64] per-row noise scale
    float* gmF   = sm + SM_GMF;    // [64] graph mask
    int*   nid   = (int*)(sm + SM_NID);

    const int b = blockIdx.x;
    const int tid = threadIdx.x;
    const int lane = tid & 31;
    const int w = tid >> 5;
    const size_t bo = (size_t)b * N_ * D_;

    // ---- load indices / mask / a-vectors ----
    if (tid < N_) {
        nid[tid] = inputs[b * N_ + tid];
        gmF[tid] = (float)gmask[b * N_ + tid];
    }
    for (int idx = tid; idx < 4 * D_; idx += 256) {
        int k = idx >> 8;
        const float* ap = (k == 0) ? a0 : (k == 1) ? a1 : (k == 2) ? a2 : a3;
        aS[idx] = ap[idx & 255];
    }
    __syncthreads();

    // ---- gather h0 ----
    for (int idx = tid; idx < N_ * D_; idx += 256) {
        int n = idx >> 8;
        h[idx] = emb[(size_t)nid[n] * D_ + (idx & 255)];
    }
    __syncthreads();

    // ---- initial star = ave_pool(h0, gm) ----
    {
        float s = 0.f, len = 0.f;
        for (int n = 0; n < N_; n++) {
            float g = gmF[n];
            s = fmaf(h[n * D_ + tid], g, s);
            len += g;
        }
        star[tid] = s / len;
    }
    __syncthreads();

    // ================= STEP loop =================
    for (int st = 0; st < STEP_; st++) {
        // ---- GAT in two row-halves (eM holds 25 rows) ----
        for (int half = 0; half < 2; half++) {
            const int hbase = half * 25;
            // e-scores: one warp per (i,j) pair
            for (int p = w; p < 25 * N_; p += 8) {
                int i = hbase + p / N_;
                int j = p - (p / N_) * N_;
                int av = __ldg(&Am[b * N_ * N_ + i * N_ + j]);
                float s;
                if (av == 0) {
                    s = -9e15f;
                } else {
                    const float4* hi4 = (const float4*)(h + i * D_);
                    const float4* hj4 = (const float4*)(h + j * D_);
                    const float4* a4  = (const float4*)(aS + (av - 1) * D_);
                    float4 x0 = hi4[2 * lane], x1 = hi4[2 * lane + 1];
                    float4 y0 = hj4[2 * lane], y1 = hj4[2 * lane + 1];
                    float4 c0 = a4[2 * lane],  c1 = a4[2 * lane + 1];
                    float t = x0.x * y0.x * c0.x + x0.y * y0.y * c0.y
                            + x0.z * y0.z * c0.z + x0.w * y0.w * c0.w
                            + x1.x * y1.x * c1.x + x1.y * y1.y * c1.y
                            + x1.z * y1.z * c1.z + x1.w * y1.w * c1.w;
                    t = wsum(t);
                    s = t > 0.f ? t : 0.2f * t;  // leaky_relu(0.2)
                }
                if (lane == 0) eM[(i - hbase) * N_ + j] = s;
            }
            __syncthreads();
            // row softmax (lane l holds e[l] and e[32+l])
            for (int r = w; r < 25; r += 8) {
                float* er = eM + r * N_;
                float e1 = er[lane];
                float e2 = (lane < 18) ? er[32 + lane] : -3.0e38f;
                float M = wmax(fmaxf(e1, e2));
                float p1 = __expf(e1 - M);
                float p2 = (lane < 18) ? __expf(e2 - M) : 0.f;
                float S = wsum(p1 + p2);
                float inv = 1.f / S;
                er[lane] = p1 * inv;
                if (lane < 18) er[32 + lane] = p2 * inv;
            }
            __syncthreads();
            // aggregate: hN[i] = sum_j alpha[i][j] * h[j]
            for (int r = w; r < 25; r += 8) {
                const float* pr = eM + r * N_;
                float4 acc0 = {0, 0, 0, 0}, acc1 = {0, 0, 0, 0};
                for (int j = 0; j < N_; j++) {
                    float p = pr[j];
                    const float4* hj4 = (const float4*)(h + j * D_);
                    acc0 = fma4(p, hj4[2 * lane], acc0);
                    acc1 = fma4(p, hj4[2 * lane + 1], acc1);
                }
                float4* o4 = (float4*)(hN + (hbase + r) * D_);
                o4[2 * lane] = acc0;
                o4[2 * lane + 1] = acc1;
            }
            __syncthreads();
        }

        // ---- per-row: sigmoid(h·star/16) and noise row norm ----
        const float* nz = noise + ((size_t)st * B_ + b) * N_ * D_;
        for (int r = w; r < N_; r += 8) {
            const float4* hv = (const float4*)(hN + r * D_);
            const float4* sv = (const float4*)star;
            const float4* nv = (const float4*)(nz + r * D_);
            float4 hv0 = hv[2 * lane], hv1 = hv[2 * lane + 1];
            float4 s0 = sv[2 * lane],  s1 = sv[2 * lane + 1];
            float4 n0 = nv[2 * lane],  n1 = nv[2 * lane + 1];
            float d1 = dot4(hv0, s0) + dot4(hv1, s1);
            float q  = dot4(n0, n0) + dot4(n1, n1);
            d1 = wsum(d1);
            q  = wsum(q);
            if (lane == 0) {
                simb[r] = 1.f / (1.f + __expf(-d1 * 0.0625f));
                nsb[r]  = 0.4f / fmaxf(sqrtf(q), 1e-12f);
            }
        }
        __syncthreads();

        // ---- elementwise mix + signed noise; accumulate hg ----
        for (int idx = tid; idx < N_ * D_; idx += 256) {
            int n = idx >> 8;
            float al = simb[n];
            float v = (1.f - al) * hN[idx] + al * star[idx & 255];
            v += sgnf(v) * nz[idx] * nsb[n];
            h[idx] = v;
            if (st == 0) g_hg[bo + idx] = v;
            else         g_hg[bo + idx] += v;
        }
        __syncthreads();

        // ---- att_pool: star update (raw exp, matches reference) ----
        for (int r = w; r < N_; r += 8) {
            const float4* hv = (const float4*)(h + r * D_);
            const float4* sv = (const float4*)star;
            float d1 = dot4(hv[2 * lane], sv[2 * lane])
                     + dot4(hv[2 * lane + 1], sv[2 * lane + 1]);
            d1 = wsum(d1);
            if (lane == 0) simb[r] = __expf(d1) * gmF[r];
        }
        __syncthreads();
        {
            float S = 0.f;
            for (int n = 0; n < N_; n++) S += simb[n];
            float inv = 1.f / (S + 1e-24f);
            float s = 0.f;
            for (int n = 0; n < N_; n++) s = fmaf(simb[n], h[n * D_ + tid], s);
            starN[tid] = s * inv;
        }
        __syncthreads();
        star[tid] = starN[tid];
        __syncthreads();
    }

    // ---- outputs: star, then highway gates ----
    ostar[b * D_ + tid] = star[tid];

    // regather h0 into hN (hN is free now; h holds final hidden hL)
    for (int idx = tid; idx < N_ * D_; idx += 256) {
        int n = idx >> 8;
        hN[idx] = emb[(size_t)nid[n] * D_ + (idx & 255)];
    }
    __syncthreads();

    const int o = tid;  // output column, 0..255
    const float i3 = 1.f / 3.f;
    const float bA = bhn[o];
    const float bB = bhn1[o];

    for (int tb = 0; tb < 2; tb++) {
        const int rbase = tb * 25;
        unsigned long long acc[25];
        // ===== gate A: sigmoid([h0, hL] @ Whn + bhn) =====
#pragma unroll
        for (int n = 0; n < 25; n++) acc[n] = 0ull;
        for (int kp = 0; kp < 128; kp++) {
            float w0 = __ldg(&Whn[(2 * kp) * D_ + o]);
            float w1 = __ldg(&Whn[(2 * kp + 1) * D_ + o]);
            unsigned long long w2 = pk2(w0, w1);
#pragma unroll
            for (int n = 0; n < 25; n++) {
                unsigned long long z =
                    *(const unsigned long long*)(hN + (rbase + n) * D_ + 2 * kp);
                fma2(acc[n], z, w2);
            }
        }
        for (int kp = 0; kp < 128; kp++) {
            float w0 = __ldg(&Whn[(D_ + 2 * kp) * D_ + o]);
            float w1 = __ldg(&Whn[(D_ + 2 * kp + 1) * D_ + o]);
            unsigned long long w2 = pk2(w0, w1);
#pragma unroll
            for (int n = 0; n < 25; n++) {
                unsigned long long z =
                    *(const unsigned long long*)(h + (rbase + n) * D_ + 2 * kp);
                fma2(acc[n], z, w2);
            }
        }
        float aA[25];
#pragma unroll
        for (int n = 0; n < 25; n++) {
            float lo, hi;
            up2(acc[n], lo, hi);
            float g = 1.f / (1.f + __expf(-(lo + hi + bA)));
            aA[n] = g;
            int row = rbase + n;
            float h0v = hN[row * D_ + o];
            float hLv = h[row * D_ + o];
            out0[bo + row * D_ + o] = g * h0v + (1.f - g) * hLv;
        }
        // ===== gate B: sigmoid([h0, hg1] @ Whn1 + bhn1), hg1 = hg_sum/3 =====
#pragma unroll
        for (int n = 0; n < 25; n++) acc[n] = 0ull;
        for (int kp = 0; kp < 128; kp++) {
            float w0 = __ldg(&Whn1[(2 * kp) * D_ + o]);
            float w1 = __ldg(&Whn1[(2 * kp + 1) * D_ + o]);
            unsigned long long w2 = pk2(w0, w1);
#pragma unroll
            for (int n = 0; n < 25; n++) {
                unsigned long long z =
                    *(const unsigned long long*)(hN + (rbase + n) * D_ + 2 * kp);
                fma2(acc[n], z, w2);
            }
        }
        for (int kp = 0; kp < 128; kp++) {
            // pre-scale hg-range weights by 1/3 so acc gets hg1 contribution
            float w0 = __ldg(&Whn1[(D_ + 2 * kp) * D_ + o]) * i3;
            float w1 = __ldg(&Whn1[(D_ + 2 * kp + 1) * D_ + o]) * i3;
            unsigned long long w2 = pk2(w0, w1);
#pragma unroll
            for (int n = 0; n < 25; n++) {
                unsigned long long z = __ldg(
                    (const unsigned long long*)(g_hg + bo + (size_t)(rbase + n) * D_ + 2 * kp));
                fma2(acc[n], z, w2);
            }
        }
#pragma unroll
        for (int n = 0; n < 25; n++) {
            float lo, hi;
            up2(acc[n], lo, hi);
            float g1 = 1.f / (1.f + __expf(-(lo + hi + bB)));
            int row = rbase + n;
            float h0v = hN[row * D_ + o];
            float hgv = g_hg[bo + row * D_ + o] * i3;
            // NB: reference uses gate-A alpha for the h0 term here
            out1[bo + row * D_ + o] = aA[n] * h0v + (1.f - g1) * hgv;
        }
    }
}

// ---------------- launch ----------------
extern "C" void kernel_launch(void* const* d_in, const int* in_sizes, int n_in,
                              void* d_out, int out_size) {
    (void)in_sizes; (void)n_in; (void)out_size;
    const int*   inputs = (const int*)d_in[0];
    const int*   Am     = (const int*)d_in[1];
    const int*   gmask  = (const int*)d_in[2];
    /* d_in[3] = item (unused by reference) */
    const float* noise  = (const float*)d_in[4];
    const float* emb    = (const float*)d_in[5];
    const float* a0     = (const float*)d_in[6];
    const float* a1     = (const float*)d_in[7];
    const float* a2     = (const float*)d_in[8];
    const float* a3     = (const float*)d_in[9];
    const float* Whn    = (const float*)d_in[10];
    const float* bhn    = (const float*)d_in[11];
    const float* Whn1   = (const float*)d_in[12];
    const float* bhn1   = (const float*)d_in[13];

    float* out  = (float*)d_out;
    float* out0 = out;                                   // [B,N,D]
    float* ostar = out + (size_t)B_ * N_ * D_;           // [B,D]
    float* out1 = ostar + (size_t)B_ * D_;               // [B,N,D]

    cudaFuncSetAttribute(sg_kernel, cudaFuncAttributeMaxDynamicSharedMemorySize,
                         SMEM_BYTES);
    sg_kernel<<<B_, 256, SMEM_BYTES>>>(inputs, Am, gmask, noise, emb,
                                       a0, a1, a2, a3, Whn, bhn, Whn1, bhn1,
                                       out0, ostar, out1);
}

// round 4
// speedup vs baseline: 1.4888x; 1.4888x over previous
#include <cuda_runtime.h>
#include <cstdint>
#include <cstddef>

#define B_ 512
#define N_ 50
#define D_ 256
#define STEP_ 3

// shared-memory layout (float offsets)
#define SM_H      0
#define SM_HN     12800
#define SM_EM     25600
#define SM_STAR   26880
#define SM_AS     27136
#define SM_SIMB   28160
#define SM_NSB    28224
#define SM_GMF    28288
#define SM_NID    28352
#define SM_FLOATS 28416
#define SMEM_BYTES (SM_FLOATS * 4)

// global scratch for hg accumulation (sum of step embeddings)
__device__ float g_hg[(size_t)B_ * N_ * D_];

// ---------------- helpers ----------------
__device__ __forceinline__ float wsum(float v) {
#pragma unroll
    for (int o = 16; o; o >>= 1) v += __shfl_xor_sync(0xffffffffu, v, o);
    return v;
}
__device__ __forceinline__ float sgnf(float x) {
    return x > 0.f ? 1.f : (x < 0.f ? -1.f : 0.f);
}
__device__ __forceinline__ float dot4(float4 a, float4 b) {
    return a.x * b.x + a.y * b.y + a.z * b.z + a.w * b.w;
}
__device__ __forceinline__ float4 fma4(float p, float4 y, float4 a) {
    a.x = fmaf(p, y.x, a.x); a.y = fmaf(p, y.y, a.y);
    a.z = fmaf(p, y.z, a.z); a.w = fmaf(p, y.w, a.w);
    return a;
}
__device__ __forceinline__ float4 mul4(float4 a, float4 b) {
    return make_float4(a.x * b.x, a.y * b.y, a.z * b.z, a.w * b.w);
}
// packed f32x2 (FFMA2) — only reachable via PTX
__device__ __forceinline__ unsigned long long pk2(float lo, float hi) {
    unsigned long long r;
    asm("mov.b64 %0, {%1, %2};" : "=l"(r) : "f"(lo), "f"(hi));
    return r;
}
__device__ __forceinline__ void fma2(unsigned long long& d, unsigned long long a,
                                     unsigned long long b) {
    asm("fma.rn.f32x2 %0, %1, %2, %0;" : "+l"(d) : "l"(a), "l"(b));
}
__device__ __forceinline__ void up2(unsigned long long v, float& lo, float& hi) {
    asm("mov.b64 {%0, %1}, %2;" : "=f"(lo), "=f"(hi) : "l"(v));
}

// one GEMV segment for the gating gates: acc[n] += z[n][k0..k0+3] * W[k0..k0+3][o]
__device__ __forceinline__ void gate_seg(unsigned long long acc[25],
                                         const float* zbase, int rbase,
                                         const float* __restrict__ Wcol) {
    for (int kp = 0; kp < 64; kp++) {
        const int k0 = 4 * kp;
        float w0 = __ldg(Wcol + (k0 + 0) * D_);
        float w1 = __ldg(Wcol + (k0 + 1) * D_);
        float w2 = __ldg(Wcol + (k0 + 2) * D_);
        float w3 = __ldg(Wcol + (k0 + 3) * D_);
        unsigned long long wA = pk2(w0, w1), wB = pk2(w2, w3);
#pragma unroll
        for (int n = 0; n < 25; n++) {
            const ulonglong2 z =
                *(const ulonglong2*)(zbase + (rbase + n) * D_ + k0);
            fma2(acc[n], z.x, wA);
            fma2(acc[n], z.y, wB);
        }
    }
}

// ---------------- fused kernel: one block per batch element ----------------
__global__ void __launch_bounds__(256, 2) sg_kernel(
    const int* __restrict__ inputs, const int* __restrict__ Am,
    const int* __restrict__ gmask, const float* __restrict__ noise,
    const float* __restrict__ emb,
    const float* __restrict__ a0, const float* __restrict__ a1,
    const float* __restrict__ a2, const float* __restrict__ a3,
    const float* __restrict__ Whn, const float* __restrict__ bhn,
    const float* __restrict__ Whn1, const float* __restrict__ bhn1,
    float* __restrict__ out0, float* __restrict__ ostar, float* __restrict__ out1)
{
    extern __shared__ float sm[];
    float* h    = sm + SM_H;      // [50][256] hidden
    float* hN   = sm + SM_HN;     // [50][256] scratch / h0
    float* eM   = sm + SM_EM;     // [25][50] attention half-matrix
    float* star = sm + SM_STAR;   // [256]
    float* aS   = sm + SM_AS;     // [4][256] a-vectors
    float* simb = sm + SM_SIMB;   // [64]
    float* nsb  = sm + SM_NSB;    // [64]
    float* gmF  = sm + SM_GMF;    // [64]
    int*   nid  = (int*)(sm + SM_NID);

    const int b = blockIdx.x;
    const int tid = threadIdx.x;
    const int lane = tid & 31;
    const int w = tid >> 5;
    const size_t bo = (size_t)b * N_ * D_;

    // ---- load indices / mask / a-vectors ----
    if (tid < N_) {
        nid[tid] = inputs[b * N_ + tid];
        gmF[tid] = (float)gmask[b * N_ + tid];
    }
    for (int idx = tid; idx < 4 * D_; idx += 256) {
        int k = idx >> 8;
        const float* ap = (k == 0) ? a0 : (k == 1) ? a1 : (k == 2) ? a2 : a3;
        aS[idx] = ap[idx & 255];
    }
    __syncthreads();

    // ---- gather h0 ----
    for (int idx = tid; idx < N_ * D_; idx += 256) {
        int n = idx >> 8;
        h[idx] = emb[(size_t)nid[n] * D_ + (idx & 255)];
    }
    __syncthreads();

    // ---- initial star = ave_pool(h0, gm) ----
    {
        float s = 0.f, len = 0.f;
        for (int n = 0; n < N_; n++) {
            float g = gmF[n];
            s = fmaf(h[n * D_ + tid], g, s);
            len += g;
        }
        star[tid] = s / len;
    }
    __syncthreads();

    // per-warp register copy of the 4 a-vectors (8 floats per lane per k)
    float4 aR[4][2];
#pragma unroll
    for (int k = 0; k < 4; k++) {
        const float4* a4 = (const float4*)(aS + k * D_);
        aR[k][0] = a4[2 * lane];
        aR[k][1] = a4[2 * lane + 1];
    }

    // ================= STEP loop =================
    for (int st = 0; st < STEP_; st++) {
        for (int half = 0; half < 2; half++) {
            const int hbase = half * 25;

            // ---- e-scores: one warp per row i, hi*a_k cached in registers ----
            for (int it = w; it < 25; it += 8) {
                const int i = hbase + it;
                const float4* hi4 = (const float4*)(h + i * D_);
                float4 x0 = hi4[2 * lane], x1 = hi4[2 * lane + 1];
                float4 ka[4][2];
#pragma unroll
                for (int k = 0; k < 4; k++) {
                    ka[k][0] = mul4(x0, aR[k][0]);
                    ka[k][1] = mul4(x1, aR[k][1]);
                }
                const int* Arow = Am + (size_t)b * N_ * N_ + i * N_;
                float* er = eM + it * N_;
                for (int j = 0; j < N_; j++) {
                    int av = __ldg(&Arow[j]);
                    float s;
                    if (av == 0) {
                        s = -9e15f;
                    } else {
                        const float4* hj4 = (const float4*)(h + j * D_);
                        float4 y0 = hj4[2 * lane], y1 = hj4[2 * lane + 1];
                        float t;
                        if (av == 1)      t = dot4(ka[0][0], y0) + dot4(ka[0][1], y1);
                        else if (av == 2) t = dot4(ka[1][0], y0) + dot4(ka[1][1], y1);
                        else if (av == 3) t = dot4(ka[2][0], y0) + dot4(ka[2][1], y1);
                        else              t = dot4(ka[3][0], y0) + dot4(ka[3][1], y1);
                        t = wsum(t);
                        s = t > 0.f ? t : 0.2f * t;  // leaky_relu(0.2)
                    }
                    if (lane == 0) er[j] = s;
                }
            }
            __syncthreads();

            // ---- row softmax (lane l holds e[l] and e[32+l]) ----
            for (int r = w; r < 25; r += 8) {
                float* er = eM + r * N_;
                float e1 = er[lane];
                float e2 = (lane < 18) ? er[32 + lane] : -3.0e38f;
                float m = fmaxf(e1, e2);
#pragma unroll
                for (int o = 16; o; o >>= 1)
                    m = fmaxf(m, __shfl_xor_sync(0xffffffffu, m, o));
                float p1 = __expf(e1 - m);
                float p2 = (lane < 18) ? __expf(e2 - m) : 0.f;
                float S = wsum(p1 + p2);
                float inv = 1.f / S;
                er[lane] = p1 * inv;
                if (lane < 18) er[32 + lane] = p2 * inv;
            }
            __syncthreads();

            // ---- aggregate 2 rows per warp: hN[i] = sum_j alpha[i][j]*h[j] ----
            for (int q = w; q < 13; q += 8) {
                const int r0 = 2 * q;
                const int r1 = 2 * q + 1;
                const bool has1 = (r1 < 25);
                const float* pr0 = eM + r0 * N_;
                const float* pr1 = eM + (has1 ? r1 : r0) * N_;
                float4 a00 = {0,0,0,0}, a01 = {0,0,0,0};
                float4 a10 = {0,0,0,0}, a11 = {0,0,0,0};
                for (int j = 0; j < N_; j++) {
                    const float4* hj4 = (const float4*)(h + j * D_);
                    float4 y0 = hj4[2 * lane], y1 = hj4[2 * lane + 1];
                    float p0 = pr0[j], p1 = pr1[j];
                    a00 = fma4(p0, y0, a00); a01 = fma4(p0, y1, a01);
                    a10 = fma4(p1, y0, a10); a11 = fma4(p1, y1, a11);
                }
                float4* o0 = (float4*)(hN + (hbase + r0) * D_);
                o0[2 * lane] = a00; o0[2 * lane + 1] = a01;
                if (has1) {
                    float4* o1 = (float4*)(hN + (hbase + r1) * D_);
                    o1[2 * lane] = a10; o1[2 * lane + 1] = a11;
                }
            }
            __syncthreads();
        }

        // ---- per-row: sigmoid(h·star/16) and noise row norm ----
        const float* nz = noise + ((size_t)st * B_ + b) * N_ * D_;
        for (int r = w; r < N_; r += 8) {
            const float4* hv = (const float4*)(hN + r * D_);
            const float4* sv = (const float4*)star;
            const float4* nv = (const float4*)(nz + r * D_);
            float4 hv0 = hv[2 * lane], hv1 = hv[2 * lane + 1];
            float4 s0 = sv[2 * lane],  s1 = sv[2 * lane + 1];
            float4 n0 = nv[2 * lane],  n1 = nv[2 * lane + 1];
            float d1 = dot4(hv0, s0) + dot4(hv1, s1);
            float q  = dot4(n0, n0) + dot4(n1, n1);
            d1 = wsum(d1);
            q  = wsum(q);
            if (lane == 0) {
                simb[r] = 1.f / (1.f + __expf(-d1 * 0.0625f));
                nsb[r]  = 0.4f / fmaxf(sqrtf(q), 1e-12f);
            }
        }
        __syncthreads();

        // ---- elementwise mix + signed noise; accumulate hg ----
        for (int idx = tid; idx < N_ * D_; idx += 256) {
            int n = idx >> 8;
            float al = simb[n];
            float v = (1.f - al) * hN[idx] + al * star[idx & 255];
            v += sgnf(v) * nz[idx] * nsb[n];
            h[idx] = v;
            if (st == 0) g_hg[bo + idx] = v;
            else         g_hg[bo + idx] += v;
        }
        __syncthreads();

        // ---- att_pool: star update (raw exp, matches reference) ----
        for (int r = w; r < N_; r += 8) {
            const float4* hv = (const float4*)(h + r * D_);
            const float4* sv = (const float4*)star;
            float d1 = dot4(hv[2 * lane], sv[2 * lane])
                     + dot4(hv[2 * lane + 1], sv[2 * lane + 1]);
            d1 = wsum(d1);
            if (lane == 0) simb[r] = __expf(d1) * gmF[r];
        }
        __syncthreads();
        {
            float S = 0.f;
            for (int n = 0; n < N_; n++) S += simb[n];
            float inv = 1.f / (S + 1e-24f);
            float s = 0.f;
            for (int n = 0; n < N_; n++) s = fmaf(simb[n], h[n * D_ + tid], s);
            hN[tid] = s * inv;  // hN is dead here — use as star staging
        }
        __syncthreads();
        star[tid] = hN[tid];
        __syncthreads();
    }

    // ---- outputs: star ----
    ostar[b * D_ + tid] = star[tid];

    // regather h0 into hN (h holds final hidden hL)
    for (int idx = tid; idx < N_ * D_; idx += 256) {
        int n = idx >> 8;
        hN[idx] = emb[(size_t)nid[n] * D_ + (idx & 255)];
    }
    __syncthreads();

    const int o = tid;  // output column, 0..255
    const float bA = bhn[o];
    const float bB = bhn1[o];

    // ===== gate A: out0 = g*h0 + (1-g)*hL ; out1 partial = g*h0 =====
    for (int tb = 0; tb < 2; tb++) {
        const int rbase = tb * 25;
        unsigned long long acc[25];
#pragma unroll
        for (int n = 0; n < 25; n++) acc[n] = 0ull;
        gate_seg(acc, hN, rbase, Whn + o);             // h0 vs W rows [0,256)
        gate_seg(acc, h,  rbase, Whn + D_ * D_ + o);   // hL vs W rows [256,512)
#pragma unroll
        for (int n = 0; n < 25; n++) {
            float lo, hi;
            up2(acc[n], lo, hi);
            float g = 1.f / (1.f + __expf(-(lo + hi + bA)));
            int row = rbase + n;
            float h0v = hN[row * D_ + o];
            float hLv = h[row * D_ + o];
            out0[bo + row * D_ + o] = g * h0v + (1.f - g) * hLv;
            out1[bo + row * D_ + o] = g * h0v;  // partial (alpha term)
        }
    }
    __syncthreads();

    // overwrite hL region with hg1 = hg_sum / 3
    for (int idx = tid; idx < N_ * D_; idx += 256)
        h[idx] = g_hg[bo + idx] * (1.f / 3.f);
    __syncthreads();

    // ===== gate B: out1 += (1-g1)*hg1 =====
    for (int tb = 0; tb < 2; tb++) {
        const int rbase = tb * 25;
        unsigned long long acc[25];
#pragma unroll
        for (int n = 0; n < 25; n++) acc[n] = 0ull;
        gate_seg(acc, hN, rbase, Whn1 + o);            // h0 vs W1 rows [0,256)
        gate_seg(acc, h,  rbase, Whn1 + D_ * D_ + o);  // hg1 vs W1 rows [256,512)
#pragma unroll
        for (int n = 0; n < 25; n++) {
            float lo, hi;
            up2(acc[n], lo, hi);
            float g1 = 1.f / (1.f + __expf(-(lo + hi + bB)));
            int row = rbase + n;
            float hgv = h[row * D_ + o];
            out1[bo + row * D_ + o] += (1.f - g1) * hgv;
        }
    }
}

// ---------------- launch ----------------
extern "C" void kernel_launch(void* const* d_in, const int* in_sizes, int n_in,
                              void* d_out, int out_size) {
    (void)in_sizes; (void)n_in; (void)out_size;
    const int*   inputs = (const int*)d_in[0];
    const int*   Am     = (const int*)d_in[1];
    const int*   gmask  = (const int*)d_in[2];
    /* d_in[3] = item (unused by reference) */
    const float* noise  = (const float*)d_in[4];
    const float* emb    = (const float*)d_in[5];
    const float* a0     = (const float*)d_in[6];
    const float* a1     = (const float*)d_in[7];
    const float* a2     = (const float*)d_in[8];
    const float* a3     = (const float*)d_in[9];
    const float* Whn    = (const float*)d_in[10];
    const float* bhn    = (const float*)d_in[11];
    const float* Whn1   = (const float*)d_in[12];
    const float* bhn1   = (const float*)d_in[13];

    float* out  = (float*)d_out;
    float* out0 = out;                                 // [B,N,D]
    float* ostar = out + (size_t)B_ * N_ * D_;         // [B,D]
    float* out1 = ostar + (size_t)B_ * D_;             // [B,N,D]

    cudaFuncSetAttribute(sg_kernel, cudaFuncAttributeMaxDynamicSharedMemorySize,
                         SMEM_BYTES);
    sg_kernel<<<B_, 256, SMEM_BYTES>>>(inputs, Am, gmask, noise, emb,
                                       a0, a1, a2, a3, Whn, bhn, Whn1, bhn1,
                                       out0, ostar, out1);
}

// round 5
// speedup vs baseline: 1.6856x; 1.1322x over previous
#include <cuda_runtime.h>
#include <cstdint>
#include <cstddef>

#define B_ 512
#define N_ 50
#define D_ 256
#define STEP_ 3

// shared-memory layout (float offsets)
#define SM_H      0        // [50][256] hidden
#define SM_HN     12800    // [50][256] gate-phase h0 buffer (unused during steps)
#define SM_EM     25600    // [50][50] attention matrix
#define SM_STAR   28100    // [256]
#define SM_SIMB   28356    // [64]
#define SM_GMF    28420    // [64]
#define SM_NID    28484    // [64]
#define SM_FLOATS 28548
#define SMEM_BYTES (SM_FLOATS * 4)

// global scratch for hg accumulation (sum of step embeddings)
__device__ float g_hg[(size_t)B_ * N_ * D_];

// ---------------- helpers ----------------
__device__ __forceinline__ float wsum(float v) {
#pragma unroll
    for (int o = 16; o; o >>= 1) v += __shfl_xor_sync(0xffffffffu, v, o);
    return v;
}
__device__ __forceinline__ float sgnf(float x) {
    return x > 0.f ? 1.f : (x < 0.f ? -1.f : 0.f);
}
__device__ __forceinline__ float dot4(float4 a, float4 b) {
    return a.x * b.x + a.y * b.y + a.z * b.z + a.w * b.w;
}
__device__ __forceinline__ float4 fma4(float p, float4 y, float4 a) {
    a.x = fmaf(p, y.x, a.x); a.y = fmaf(p, y.y, a.y);
    a.z = fmaf(p, y.z, a.z); a.w = fmaf(p, y.w, a.w);
    return a;
}
__device__ __forceinline__ float4 mul4(float4 a, float4 b) {
    return make_float4(a.x * b.x, a.y * b.y, a.z * b.z, a.w * b.w);
}
// packed f32x2 (FFMA2) — only reachable via PTX
__device__ __forceinline__ unsigned long long pk2(float lo, float hi) {
    unsigned long long r;
    asm("mov.b64 %0, {%1, %2};" : "=l"(r) : "f"(lo), "f"(hi));
    return r;
}
__device__ __forceinline__ void fma2(unsigned long long& d, unsigned long long a,
                                     unsigned long long b) {
    asm("fma.rn.f32x2 %0, %1, %2, %0;" : "+l"(d) : "l"(a), "l"(b));
}
__device__ __forceinline__ void up2(unsigned long long v, float& lo, float& hi) {
    asm("mov.b64 {%0, %1}, %2;" : "=f"(lo), "=f"(hi) : "l"(v));
}

// one GEMV segment for the gating gates: acc[n] += z[n][k0..k0+3] * W[k0..k0+3][o]
__device__ __forceinline__ void gate_seg(unsigned long long acc[25],
                                         const float* zbase, int rbase,
                                         const float* __restrict__ Wcol) {
    for (int kp = 0; kp < 64; kp++) {
        const int k0 = 4 * kp;
        float w0 = __ldg(Wcol + (k0 + 0) * D_);
        float w1 = __ldg(Wcol + (k0 + 1) * D_);
        float w2 = __ldg(Wcol + (k0 + 2) * D_);
        float w3 = __ldg(Wcol + (k0 + 3) * D_);
        unsigned long long wA = pk2(w0, w1), wB = pk2(w2, w3);
#pragma unroll
        for (int n = 0; n < 25; n++) {
            const ulonglong2 z =
                *(const ulonglong2*)(zbase + (rbase + n) * D_ + k0);
            fma2(acc[n], z.x, wA);
            fma2(acc[n], z.y, wB);
        }
    }
}

// ---------------- fused kernel: one block per batch element ----------------
__global__ void __launch_bounds__(256, 2) sg_kernel(
    const int* __restrict__ inputs, const int* __restrict__ Am,
    const int* __restrict__ gmask, const float* __restrict__ noise,
    const float* __restrict__ emb,
    const float* __restrict__ a0, const float* __restrict__ a1,
    const float* __restrict__ a2, const float* __restrict__ a3,
    const float* __restrict__ Whn, const float* __restrict__ bhn,
    const float* __restrict__ Whn1, const float* __restrict__ bhn1,
    float* __restrict__ out0, float* __restrict__ ostar, float* __restrict__ out1)
{
    extern __shared__ float sm[];
    float* h    = sm + SM_H;
    float* hN   = sm + SM_HN;
    float* eM   = sm + SM_EM;
    float* star = sm + SM_STAR;
    float* simb = sm + SM_SIMB;
    float* gmF  = sm + SM_GMF;
    int*   nid  = (int*)(sm + SM_NID);

    const int b = blockIdx.x;
    const int tid = threadIdx.x;
    const int lane = tid & 31;
    const int w = tid >> 5;
    const size_t bo = (size_t)b * N_ * D_;

    // ---- indices / mask ----
    if (tid < N_) {
        nid[tid] = inputs[b * N_ + tid];
        gmF[tid] = (float)gmask[b * N_ + tid];
    }
    __syncthreads();

    // ---- gather h0 ----
    for (int idx = tid; idx < N_ * D_; idx += 256) {
        int n = idx >> 8;
        h[idx] = emb[(size_t)nid[n] * D_ + (idx & 255)];
    }
    __syncthreads();

    // ---- initial star = ave_pool(h0, gm) ----
    {
        float s = 0.f, len = 0.f;
        for (int n = 0; n < N_; n++) {
            float g = gmF[n];
            s = fmaf(h[n * D_ + tid], g, s);
            len += g;
        }
        star[tid] = s / len;
    }
    __syncthreads();

    // a-vectors straight to registers (8 floats per lane per k)
    float4 aR[4][2];
    aR[0][0] = __ldg((const float4*)a0 + 2 * lane);
    aR[0][1] = __ldg((const float4*)a0 + 2 * lane + 1);
    aR[1][0] = __ldg((const float4*)a1 + 2 * lane);
    aR[1][1] = __ldg((const float4*)a1 + 2 * lane + 1);
    aR[2][0] = __ldg((const float4*)a2 + 2 * lane);
    aR[2][1] = __ldg((const float4*)a2 + 2 * lane + 1);
    aR[3][0] = __ldg((const float4*)a3 + 2 * lane);
    aR[3][1] = __ldg((const float4*)a3 + 2 * lane + 1);

    // ================= STEP loop =================
    for (int st = 0; st < STEP_; st++) {
        // ---- e-scores: warp per row i, j processed in pairs ----
        for (int i = w; i < N_; i += 8) {
            const float4* hi4 = (const float4*)(h + i * D_);
            float4 x0 = hi4[2 * lane], x1 = hi4[2 * lane + 1];
            float4 ka[4][2];
#pragma unroll
            for (int k = 0; k < 4; k++) {
                ka[k][0] = mul4(x0, aR[k][0]);
                ka[k][1] = mul4(x1, aR[k][1]);
            }
            const int* Arow = Am + (size_t)b * N_ * N_ + i * N_;
            float* er = eM + i * N_;
            for (int j = 0; j < N_; j += 2) {
                int2 av = *(const int2*)(Arow + j);
                if ((av.x | av.y) == 0) {
                    if (lane == 0) { er[j] = -9e15f; er[j + 1] = -9e15f; }
                    continue;
                }
                float p0 = 0.f, p1 = 0.f;
                if (av.x) {
                    const float4* y4 = (const float4*)(h + j * D_);
                    float4 y0 = y4[2 * lane], y1 = y4[2 * lane + 1];
                    float4 c0, c1;
                    switch (av.x) {
                        case 1:  c0 = ka[0][0]; c1 = ka[0][1]; break;
                        case 2:  c0 = ka[1][0]; c1 = ka[1][1]; break;
                        case 3:  c0 = ka[2][0]; c1 = ka[2][1]; break;
                        default: c0 = ka[3][0]; c1 = ka[3][1]; break;
                    }
                    p0 = dot4(c0, y0) + dot4(c1, y1);
                }
                if (av.y) {
                    const float4* y4 = (const float4*)(h + (j + 1) * D_);
                    float4 y0 = y4[2 * lane], y1 = y4[2 * lane + 1];
                    float4 c0, c1;
                    switch (av.y) {
                        case 1:  c0 = ka[0][0]; c1 = ka[0][1]; break;
                        case 2:  c0 = ka[1][0]; c1 = ka[1][1]; break;
                        case 3:  c0 = ka[2][0]; c1 = ka[2][1]; break;
                        default: c0 = ka[3][0]; c1 = ka[3][1]; break;
                    }
                    p1 = dot4(c0, y0) + dot4(c1, y1);
                }
                // two interleaved butterfly reductions
#pragma unroll
                for (int o = 16; o; o >>= 1) {
                    p0 += __shfl_xor_sync(0xffffffffu, p0, o);
                    p1 += __shfl_xor_sync(0xffffffffu, p1, o);
                }
                if (lane == 0) {
                    er[j]     = av.x ? (p0 > 0.f ? p0 : 0.2f * p0) : -9e15f;
                    er[j + 1] = av.y ? (p1 > 0.f ? p1 : 0.2f * p1) : -9e15f;
                }
            }
        }
        __syncthreads();

        // ---- row softmax in place ----
        for (int r = w; r < N_; r += 8) {
            float* er = eM + r * N_;
            float e1 = er[lane];
            float e2 = (lane < 18) ? er[32 + lane] : -3.0e38f;
            float m = fmaxf(e1, e2);
#pragma unroll
            for (int o = 16; o; o >>= 1)
                m = fmaxf(m, __shfl_xor_sync(0xffffffffu, m, o));
            float p1 = __expf(e1 - m);
            float p2 = (lane < 18) ? __expf(e2 - m) : 0.f;
            float S = wsum(p1 + p2);
            float inv = 1.f / S;
            er[lane] = p1 * inv;
            if (lane < 18) er[32 + lane] = p2 * inv;
        }
        __syncthreads();

        // ---- aggregation into registers: rows r = w + 8q ----
        float4 acc[7][2];
#pragma unroll
        for (int q = 0; q < 7; q++) {
            acc[q][0] = make_float4(0, 0, 0, 0);
            acc[q][1] = make_float4(0, 0, 0, 0);
        }
        for (int j = 0; j < N_; j++) {
            const float4* y4 = (const float4*)(h + j * D_);
            float4 y0 = y4[2 * lane], y1 = y4[2 * lane + 1];
#pragma unroll
            for (int q = 0; q < 7; q++) {
                int r = w + 8 * q;
                if (r < N_) {
                    float p = eM[r * N_ + j];
                    acc[q][0] = fma4(p, y0, acc[q][0]);
                    acc[q][1] = fma4(p, y1, acc[q][1]);
                }
            }
        }

        // star cached in registers (old star)
        const float4* s4 = (const float4*)star;
        float4 s0 = s4[2 * lane], s1 = s4[2 * lane + 1];

        // ---- fused: sigmoid-mix + signed noise + att_pool numerator ----
        const float* nz = noise + ((size_t)st * B_ + b) * N_ * D_;
#pragma unroll
        for (int q = 0; q < 7; q++) {
            int r = w + 8 * q;
            if (r < N_) {
                float sim = wsum(dot4(acc[q][0], s0) + dot4(acc[q][1], s1));
                float al = 1.f / (1.f + __expf(-sim * 0.0625f));
                float om = 1.f - al;
                const float4* n4 = (const float4*)(nz + r * D_);
                float4 n0 = __ldg(n4 + 2 * lane), n1 = __ldg(n4 + 2 * lane + 1);
                float qn = wsum(dot4(n0, n0) + dot4(n1, n1));
                float sc = 0.4f / fmaxf(sqrtf(qn), 1e-12f);
                float4 v0, v1;
                v0.x = om * acc[q][0].x + al * s0.x;
                v0.y = om * acc[q][0].y + al * s0.y;
                v0.z = om * acc[q][0].z + al * s0.z;
                v0.w = om * acc[q][0].w + al * s0.w;
                v1.x = om * acc[q][1].x + al * s1.x;
                v1.y = om * acc[q][1].y + al * s1.y;
                v1.z = om * acc[q][1].z + al * s1.z;
                v1.w = om * acc[q][1].w + al * s1.w;
                v0.x = fmaf(sgnf(v0.x) * sc, n0.x, v0.x);
                v0.y = fmaf(sgnf(v0.y) * sc, n0.y, v0.y);
                v0.z = fmaf(sgnf(v0.z) * sc, n0.z, v0.z);
                v0.w = fmaf(sgnf(v0.w) * sc, n0.w, v0.w);
                v1.x = fmaf(sgnf(v1.x) * sc, n1.x, v1.x);
                v1.y = fmaf(sgnf(v1.y) * sc, n1.y, v1.y);
                v1.z = fmaf(sgnf(v1.z) * sc, n1.z, v1.z);
                v1.w = fmaf(sgnf(v1.w) * sc, n1.w, v1.w);
                // att_pool numerator with NEW hidden vs OLD star
                float d1 = wsum(dot4(v0, s0) + dot4(v1, s1));
                if (lane == 0) simb[r] = __expf(d1) * gmF[r];
                acc[q][0] = v0;
                acc[q][1] = v1;
            }
        }
        __syncthreads();  // all warps done reading old h / eM

        // ---- write new h + accumulate hg ----
#pragma unroll
        for (int q = 0; q < 7; q++) {
            int r = w + 8 * q;
            if (r < N_) {
                float4* h4 = (float4*)(h + r * D_);
                h4[2 * lane] = acc[q][0];
                h4[2 * lane + 1] = acc[q][1];
                float4* g4 = (float4*)(g_hg + bo + (size_t)r * D_);
                if (st == 0) {
                    g4[2 * lane] = acc[q][0];
                    g4[2 * lane + 1] = acc[q][1];
                } else {
                    float4 t0 = g4[2 * lane], t1 = g4[2 * lane + 1];
                    t0.x += acc[q][0].x; t0.y += acc[q][0].y;
                    t0.z += acc[q][0].z; t0.w += acc[q][0].w;
                    t1.x += acc[q][1].x; t1.y += acc[q][1].y;
                    t1.z += acc[q][1].z; t1.w += acc[q][1].w;
                    g4[2 * lane] = t0;
                    g4[2 * lane + 1] = t1;
                }
            }
        }
        __syncthreads();

        // ---- star = att_pool weighted sum ----
        {
            float S = 0.f;
            for (int n = 0; n < N_; n++) S += simb[n];
            float inv = 1.f / (S + 1e-24f);
            float s = 0.f;
            for (int n = 0; n < N_; n++) s = fmaf(simb[n], h[n * D_ + tid], s);
            star[tid] = s * inv;
        }
        __syncthreads();
    }

    // ---- outputs: star ----
    ostar[b * D_ + tid] = star[tid];

    // regather h0 into hN (h holds final hidden hL)
    for (int idx = tid; idx < N_ * D_; idx += 256) {
        int n = idx >> 8;
        hN[idx] = emb[(size_t)nid[n] * D_ + (idx & 255)];
    }
    __syncthreads();

    const int o = tid;  // output column, 0..255
    const float bA = bhn[o];
    const float bB = bhn1[o];

    // ===== gate A: out0 = g*h0 + (1-g)*hL ; out1 partial = g*h0 =====
    for (int tb = 0; tb < 2; tb++) {
        const int rbase = tb * 25;
        unsigned long long acc[25];
#pragma unroll
        for (int n = 0; n < 25; n++) acc[n] = 0ull;
        gate_seg(acc, hN, rbase, Whn + o);             // h0 vs W rows [0,256)
        gate_seg(acc, h,  rbase, Whn + D_ * D_ + o);   // hL vs W rows [256,512)
#pragma unroll
        for (int n = 0; n < 25; n++) {
            float lo, hi;
            up2(acc[n], lo, hi);
            float g = 1.f / (1.f + __expf(-(lo + hi + bA)));
            int row = rbase + n;
            float h0v = hN[row * D_ + o];
            float hLv = h[row * D_ + o];
            out0[bo + row * D_ + o] = g * h0v + (1.f - g) * hLv;
            out1[bo + row * D_ + o] = g * h0v;  // partial (alpha term)
        }
    }
    __syncthreads();

    // overwrite hL region with hg1 = hg_sum / 3
    for (int idx = tid; idx < N_ * D_; idx += 256)
        h[idx] = g_hg[bo + idx] * (1.f / 3.f);
    __syncthreads();

    // ===== gate B: out1 += (1-g1)*hg1 =====
    for (int tb = 0; tb < 2; tb++) {
        const int rbase = tb * 25;
        unsigned long long acc[25];
#pragma unroll
        for (int n = 0; n < 25; n++) acc[n] = 0ull;
        gate_seg(acc, hN, rbase, Whn1 + o);            // h0 vs W1 rows [0,256)
        gate_seg(acc, h,  rbase, Whn1 + D_ * D_ + o);  // hg1 vs W1 rows [256,512)
#pragma unroll
        for (int n = 0; n < 25; n++) {
            float lo, hi;
            up2(acc[n], lo, hi);
            float g1 = 1.f / (1.f + __expf(-(lo + hi + bB)));
            int row = rbase + n;
            float hgv = h[row * D_ + o];
            out1[bo + row * D_ + o] += (1.f - g1) * hgv;
        }
    }
}

// ---------------- launch ----------------
extern "C" void kernel_launch(void* const* d_in, const int* in_sizes, int n_in,
                              void* d_out, int out_size) {
    (void)in_sizes; (void)n_in; (void)out_size;
    const int*   inputs = (const int*)d_in[0];
    const int*   Am     = (const int*)d_in[1];
    const int*   gmask  = (const int*)d_in[2];
    /* d_in[3] = item (unused by reference) */
    const float* noise  = (const float*)d_in[4];
    const float* emb    = (const float*)d_in[5];
    const float* a0     = (const float*)d_in[6];
    const float* a1     = (const float*)d_in[7];
    const float* a2     = (const float*)d_in[8];
    const float* a3     = (const float*)d_in[9];
    const float* Whn    = (const float*)d_in[10];
    const float* bhn    = (const float*)d_in[11];
    const float* Whn1   = (const float*)d_in[12];
    const float* bhn1   = (const float*)d_in[13];

    float* out  = (float*)d_out;
    float* out0 = out;                                 // [B,N,D]
    float* ostar = out + (size_t)B_ * N_ * D_;         // [B,D]
    float* out1 = ostar + (size_t)B_ * D_;             // [B,N,D]

    cudaFuncSetAttribute(sg_kernel, cudaFuncAttributeMaxDynamicSharedMemorySize,
                         SMEM_BYTES);
    sg_kernel<<<B_, 256, SMEM_BYTES>>>(inputs, Am, gmask, noise, emb,
                                       a0, a1, a2, a3, Whn, bhn, Whn1, bhn1,
                                       out0, ostar, out1);
}

// round 7
// speedup vs baseline: 1.7912x; 1.0626x over previous
#include <cuda_runtime.h>
#include <cstdint>
#include <cstddef>

#define B_ 512
#define N_ 50
#define D_ 256
#define STEP_ 3

// shared-memory layout (float offsets)
#define SM_H      0        // [50][256] hidden
#define SM_HN     12800    // [50][256] noise slab (steps) / h0 buffer (gating)
#define SM_EM     25600    // [50][50] attention matrix
#define SM_STAR   28100    // [256]
#define SM_SIMB   28356    // [64]
#define SM_GMF    28420    // [64]
#define SM_NID    28484    // [64]
#define SM_FLOATS 28548
#define SMEM_BYTES (SM_FLOATS * 4)

// global scratch for hg accumulation (sum of step embeddings)
__device__ float g_hg[(size_t)B_ * N_ * D_];

// ---------------- helpers ----------------
__device__ __forceinline__ float wsum(float v) {
#pragma unroll
    for (int o = 16; o; o >>= 1) v += __shfl_xor_sync(0xffffffffu, v, o);
    return v;
}
__device__ __forceinline__ float sgnf(float x) {
    return x > 0.f ? 1.f : (x < 0.f ? -1.f : 0.f);
}
__device__ __forceinline__ float dot4(float4 a, float4 b) {
    return a.x * b.x + a.y * b.y + a.z * b.z + a.w * b.w;
}
__device__ __forceinline__ float4 fma4(float p, float4 y, float4 a) {
    a.x = fmaf(p, y.x, a.x); a.y = fmaf(p, y.y, a.y);
    a.z = fmaf(p, y.z, a.z); a.w = fmaf(p, y.w, a.w);
    return a;
}
__device__ __forceinline__ float4 mul4(float4 a, float4 b) {
    return make_float4(a.x * b.x, a.y * b.y, a.z * b.z, a.w * b.w);
}
// packed f32x2 (FFMA2) — only reachable via PTX
__device__ __forceinline__ unsigned long long pk2(float lo, float hi) {
    unsigned long long r;
    asm("mov.b64 %0, {%1, %2};" : "=l"(r) : "f"(lo), "f"(hi));
    return r;
}
__device__ __forceinline__ void fma2(unsigned long long& d, unsigned long long a,
                                     unsigned long long b) {
    asm("fma.rn.f32x2 %0, %1, %2, %0;" : "+l"(d) : "l"(a), "l"(b));
}
__device__ __forceinline__ void up2(unsigned long long v, float& lo, float& hi) {
    asm("mov.b64 {%0, %1}, %2;" : "=f"(lo), "=f"(hi) : "l"(v));
}
__device__ __forceinline__ void cp16(uint32_t saddr, const void* gaddr) {
    asm volatile("cp.async.cg.shared.global [%0], [%1], 16;"
                 :: "r"(saddr), "l"(gaddr));
}

// per-j masked dot against register-cached ka (av is warp-uniform)
__device__ __forceinline__ float edot(int av, const float* hj, int lane,
                                      const float4 ka[4][2]) {
    const float4* y4 = (const float4*)hj;
    float4 y0 = y4[2 * lane], y1 = y4[2 * lane + 1];
    float4 c0, c1;
    switch (av) {
        case 1:  c0 = ka[0][0]; c1 = ka[0][1]; break;
        case 2:  c0 = ka[1][0]; c1 = ka[1][1]; break;
        case 3:  c0 = ka[2][0]; c1 = ka[2][1]; break;
        default: c0 = ka[3][0]; c1 = ka[3][1]; break;
    }
    return dot4(c0, y0) + dot4(c1, y1);
}

// one GEMV segment for the gating gates: acc[n] += z[n][k0..k0+3] * W[k0..k0+3][o]
__device__ __forceinline__ void gate_seg(unsigned long long acc[25],
                                         const float* zbase, int rbase,
                                         const float* __restrict__ Wcol) {
    for (int kp = 0; kp < 64; kp++) {
        const int k0 = 4 * kp;
        float w0 = __ldg(Wcol + (k0 + 0) * D_);
        float w1 = __ldg(Wcol + (k0 + 1) * D_);
        float w2 = __ldg(Wcol + (k0 + 2) * D_);
        float w3 = __ldg(Wcol + (k0 + 3) * D_);
        unsigned long long wA = pk2(w0, w1), wB = pk2(w2, w3);
#pragma unroll
        for (int n = 0; n < 25; n++) {
            const ulonglong2 z =
                *(const ulonglong2*)(zbase + (rbase + n) * D_ + k0);
            fma2(acc[n], z.x, wA);
            fma2(acc[n], z.y, wB);
        }
    }
}

// ---------------- fused kernel: one block per batch element ----------------
__global__ void __launch_bounds__(256, 2) sg_kernel(
    const int* __restrict__ inputs, const int* __restrict__ Am,
    const int* __restrict__ gmask, const float* __restrict__ noise,
    const float* __restrict__ emb,
    const float* __restrict__ a0, const float* __restrict__ a1,
    const float* __restrict__ a2, const float* __restrict__ a3,
    const float* __restrict__ Whn, const float* __restrict__ bhn,
    const float* __restrict__ Whn1, const float* __restrict__ bhn1,
    float* __restrict__ out0, float* __restrict__ ostar, float* __restrict__ out1)
{
    extern __shared__ float sm[];
    float* h    = sm + SM_H;
    float* hN   = sm + SM_HN;   // noise slab during steps, h0 in gating
    float* eM   = sm + SM_EM;
    float* star = sm + SM_STAR;
    float* simb = sm + SM_SIMB;
    float* gmF  = sm + SM_GMF;
    int*   nid  = (int*)(sm + SM_NID);

    const int b = blockIdx.x;
    const int tid = threadIdx.x;
    const int lane = tid & 31;
    const int w = tid >> 5;
    const size_t bo = (size_t)b * N_ * D_;

    // ---- indices / mask ----
    if (tid < N_) {
        nid[tid] = inputs[b * N_ + tid];
        gmF[tid] = (float)gmask[b * N_ + tid];
    }
    __syncthreads();

    // ---- gather h0 ----
    for (int idx = tid; idx < N_ * D_; idx += 256) {
        int n = idx >> 8;
        h[idx] = emb[(size_t)nid[n] * D_ + (idx & 255)];
    }
    __syncthreads();

    // ---- initial star = ave_pool(h0, gm) ----
    {
        float s = 0.f, len = 0.f;
        for (int n = 0; n < N_; n++) {
            float g = gmF[n];
            s = fmaf(h[n * D_ + tid], g, s);
            len += g;
        }
        star[tid] = s / len;
    }
    __syncthreads();

    const uint32_t hN_s = (uint32_t)__cvta_generic_to_shared(hN);

    // ================= STEP loop =================
    for (int st = 0; st < STEP_; st++) {
        // ---- prefetch this step's noise slab into hN (overlaps e+agg) ----
        {
            const float* gsrc = noise + ((size_t)st * B_ + b) * N_ * D_;
            for (int c = tid; c < N_ * D_ / 4; c += 256)
                cp16(hN_s + c * 16, gsrc + c * 4);
            asm volatile("cp.async.commit_group;" ::: "memory");
        }

        // ---- e-scores + row softmax: one warp per row i ----
        for (int i = w; i < N_; i += 8) {
            const float4* hi4 = (const float4*)(h + i * D_);
            float4 x0 = hi4[2 * lane], x1 = hi4[2 * lane + 1];
            float4 ka[4][2];
            ka[0][0] = mul4(x0, __ldg((const float4*)a0 + 2 * lane));
            ka[0][1] = mul4(x1, __ldg((const float4*)a0 + 2 * lane + 1));
            ka[1][0] = mul4(x0, __ldg((const float4*)a1 + 2 * lane));
            ka[1][1] = mul4(x1, __ldg((const float4*)a1 + 2 * lane + 1));
            ka[2][0] = mul4(x0, __ldg((const float4*)a2 + 2 * lane));
            ka[2][1] = mul4(x1, __ldg((const float4*)a2 + 2 * lane + 1));
            ka[3][0] = mul4(x0, __ldg((const float4*)a3 + 2 * lane));
            ka[3][1] = mul4(x1, __ldg((const float4*)a3 + 2 * lane + 1));

            const int* Arow = Am + (size_t)b * N_ * N_ + i * N_;
            float* er = eM + i * N_;

            // 12 groups of 4 j's (two int2 loads: row base is only 8B-aligned),
            // 4 interleaved reduction chains
            for (int jb = 0; jb < 48; jb += 4) {
                const int2 avlo = *(const int2*)(Arow + jb);
                const int2 avhi = *(const int2*)(Arow + jb + 2);
                const float* hb = h + jb * D_;
                float p0 = 0.f, p1 = 0.f, p2 = 0.f, p3 = 0.f;
                if (avlo.x) p0 = edot(avlo.x, hb,          lane, ka);
                if (avlo.y) p1 = edot(avlo.y, hb + D_,     lane, ka);
                if (avhi.x) p2 = edot(avhi.x, hb + 2 * D_, lane, ka);
                if (avhi.y) p3 = edot(avhi.y, hb + 3 * D_, lane, ka);
#pragma unroll
                for (int o = 16; o; o >>= 1) {
                    p0 += __shfl_xor_sync(0xffffffffu, p0, o);
                    p1 += __shfl_xor_sync(0xffffffffu, p1, o);
                    p2 += __shfl_xor_sync(0xffffffffu, p2, o);
                    p3 += __shfl_xor_sync(0xffffffffu, p3, o);
                }
                if (lane == 0) {
                    er[jb + 0] = avlo.x ? (p0 > 0.f ? p0 : 0.2f * p0) : -9e15f;
                    er[jb + 1] = avlo.y ? (p1 > 0.f ? p1 : 0.2f * p1) : -9e15f;
                    er[jb + 2] = avhi.x ? (p2 > 0.f ? p2 : 0.2f * p2) : -9e15f;
                    er[jb + 3] = avhi.y ? (p3 > 0.f ? p3 : 0.2f * p3) : -9e15f;
                }
            }
            {   // tail j = 48, 49
                const int2 av = *(const int2*)(Arow + 48);
                float p0 = 0.f, p1 = 0.f;
                if (av.x) p0 = edot(av.x, h + 48 * D_, lane, ka);
                if (av.y) p1 = edot(av.y, h + 49 * D_, lane, ka);
#pragma unroll
                for (int o = 16; o; o >>= 1) {
                    p0 += __shfl_xor_sync(0xffffffffu, p0, o);
                    p1 += __shfl_xor_sync(0xffffffffu, p1, o);
                }
                if (lane == 0) {
                    er[48] = av.x ? (p0 > 0.f ? p0 : 0.2f * p0) : -9e15f;
                    er[49] = av.y ? (p1 > 0.f ? p1 : 0.2f * p1) : -9e15f;
                }
            }
            __syncwarp();
            // in-place row softmax
            {
                float e1 = er[lane];
                float e2 = (lane < 18) ? er[32 + lane] : -3.0e38f;
                float m = fmaxf(e1, e2);
#pragma unroll
                for (int o = 16; o; o >>= 1)
                    m = fmaxf(m, __shfl_xor_sync(0xffffffffu, m, o));
                float q1 = __expf(e1 - m);
                float q2 = (lane < 18) ? __expf(e2 - m) : 0.f;
                float S = wsum(q1 + q2);
                float inv = 1.f / S;
                er[lane] = q1 * inv;
                if (lane < 18) er[32 + lane] = q2 * inv;
            }
        }
        __syncthreads();

        // ---- aggregation into registers: rows r = w + 8q ----
        float4 acc[7][2];
#pragma unroll
        for (int q = 0; q < 7; q++) {
            acc[q][0] = make_float4(0, 0, 0, 0);
            acc[q][1] = make_float4(0, 0, 0, 0);
        }
        {
            const float* e0 = eM + (w + 0) * N_;
            const float* e1 = eM + (w + 8) * N_;
            const float* e2 = eM + (w + 16) * N_;
            const float* e3 = eM + (w + 24) * N_;
            const float* e4 = eM + (w + 32) * N_;
            const float* e5 = eM + (w + 40) * N_;
            const float* e6 = (w + 48 < N_) ? eM + (w + 48) * N_ : e0;
            const bool has6 = (w + 48 < N_);
            for (int j = 0; j < N_; j++) {
                const float4* y4 = (const float4*)(h + j * D_);
                float4 y0 = y4[2 * lane], y1 = y4[2 * lane + 1];
                float p;
                p = e0[j]; acc[0][0] = fma4(p, y0, acc[0][0]); acc[0][1] = fma4(p, y1, acc[0][1]);
                p = e1[j]; acc[1][0] = fma4(p, y0, acc[1][0]); acc[1][1] = fma4(p, y1, acc[1][1]);
                p = e2[j]; acc[2][0] = fma4(p, y0, acc[2][0]); acc[2][1] = fma4(p, y1, acc[2][1]);
                p = e3[j]; acc[3][0] = fma4(p, y0, acc[3][0]); acc[3][1] = fma4(p, y1, acc[3][1]);
                p = e4[j]; acc[4][0] = fma4(p, y0, acc[4][0]); acc[4][1] = fma4(p, y1, acc[4][1]);
                p = e5[j]; acc[5][0] = fma4(p, y0, acc[5][0]); acc[5][1] = fma4(p, y1, acc[5][1]);
                if (has6) { p = e6[j]; acc[6][0] = fma4(p, y0, acc[6][0]); acc[6][1] = fma4(p, y1, acc[6][1]); }
            }
        }

        // noise slab must be in SMEM now; also fences agg h-reads before h writes
        asm volatile("cp.async.wait_group 0;" ::: "memory");
        __syncthreads();

        // star cached in registers (old star)
        const float4* s4 = (const float4*)star;
        float4 s0 = s4[2 * lane], s1 = s4[2 * lane + 1];

        // ---- stage A: sim + noise-norm reductions, q-pairs interleaved ----
        float alpha[7], nscale[7];
#pragma unroll
        for (int q0 = 0; q0 < 7; q0 += 2) {
            const int r0 = w + 8 * q0;
            const int r1 = r0 + 8;
            const bool v0 = (r0 < N_);
            const bool v1 = (q0 + 1 < 7) && (r1 < N_);
            float pa = 0.f, pb = 0.f, pc = 0.f, pd = 0.f;
            if (v0) {
                pa = dot4(acc[q0][0], s0) + dot4(acc[q0][1], s1);
                const float4* m4 = (const float4*)(hN + r0 * D_);
                float4 m0 = m4[2 * lane], m1 = m4[2 * lane + 1];
                pb = dot4(m0, m0) + dot4(m1, m1);
            }
            if (v1) {
                pc = dot4(acc[q0 + 1][0], s0) + dot4(acc[q0 + 1][1], s1);
                const float4* m4 = (const float4*)(hN + r1 * D_);
                float4 m0 = m4[2 * lane], m1 = m4[2 * lane + 1];
                pd = dot4(m0, m0) + dot4(m1, m1);
            }
#pragma unroll
            for (int o = 16; o; o >>= 1) {
                pa += __shfl_xor_sync(0xffffffffu, pa, o);
                pb += __shfl_xor_sync(0xffffffffu, pb, o);
                pc += __shfl_xor_sync(0xffffffffu, pc, o);
                pd += __shfl_xor_sync(0xffffffffu, pd, o);
            }
            alpha[q0]  = 1.f / (1.f + __expf(-pa * 0.0625f));
            nscale[q0] = 0.4f / fmaxf(sqrtf(pb), 1e-12f);
            if (q0 + 1 < 7) {
                alpha[q0 + 1]  = 1.f / (1.f + __expf(-pc * 0.0625f));
                nscale[q0 + 1] = 0.4f / fmaxf(sqrtf(pd), 1e-12f);
            }
        }

        // ---- stage B: mix + signed noise (no reductions) ----
        float pd1[7];
#pragma unroll
        for (int q = 0; q < 7; q++) {
            const int r = w + 8 * q;
            pd1[q] = 0.f;
            if (r < N_) {
                const float al = alpha[q], om = 1.f - al, sc = nscale[q];
                const float4* m4 = (const float4*)(hN + r * D_);
                float4 n0 = m4[2 * lane], n1 = m4[2 * lane + 1];
                float4 v0, v1;
                v0.x = om * acc[q][0].x + al * s0.x;
                v0.y = om * acc[q][0].y + al * s0.y;
                v0.z = om * acc[q][0].z + al * s0.z;
                v0.w = om * acc[q][0].w + al * s0.w;
                v1.x = om * acc[q][1].x + al * s1.x;
                v1.y = om * acc[q][1].y + al * s1.y;
                v1.z = om * acc[q][1].z + al * s1.z;
                v1.w = om * acc[q][1].w + al * s1.w;
                v0.x = fmaf(sgnf(v0.x) * sc, n0.x, v0.x);
                v0.y = fmaf(sgnf(v0.y) * sc, n0.y, v0.y);
                v0.z = fmaf(sgnf(v0.z) * sc, n0.z, v0.z);
                v0.w = fmaf(sgnf(v0.w) * sc, n0.w, v0.w);
                v1.x = fmaf(sgnf(v1.x) * sc, n1.x, v1.x);
                v1.y = fmaf(sgnf(v1.y) * sc, n1.y, v1.y);
                v1.z = fmaf(sgnf(v1.z) * sc, n1.z, v1.z);
                v1.w = fmaf(sgnf(v1.w) * sc, n1.w, v1.w);
                acc[q][0] = v0;
                acc[q][1] = v1;
                pd1[q] = dot4(v0, s0) + dot4(v1, s1);  // att_pool numerator
            }
        }

        // ---- stage C: all 7 d1 chains in one interleaved butterfly ----
#pragma unroll
        for (int o = 16; o; o >>= 1) {
#pragma unroll
            for (int q = 0; q < 7; q++)
                pd1[q] += __shfl_xor_sync(0xffffffffu, pd1[q], o);
        }
        if (lane == 0) {
#pragma unroll
            for (int q = 0; q < 7; q++) {
                const int r = w + 8 * q;
                if (r < N_) simb[r] = __expf(pd1[q]) * gmF[r];
            }
        }

        // ---- write new h + accumulate hg ----
#pragma unroll
        for (int q = 0; q < 7; q++) {
            const int r = w + 8 * q;
            if (r < N_) {
                float4* h4 = (float4*)(h + r * D_);
                h4[2 * lane] = acc[q][0];
                h4[2 * lane + 1] = acc[q][1];
                float4* g4 = (float4*)(g_hg + bo + (size_t)r * D_);
                if (st == 0) {
                    g4[2 * lane] = acc[q][0];
                    g4[2 * lane + 1] = acc[q][1];
                } else {
                    float4 t0 = g4[2 * lane], t1 = g4[2 * lane + 1];
                    t0.x += acc[q][0].x; t0.y += acc[q][0].y;
                    t0.z += acc[q][0].z; t0.w += acc[q][0].w;
                    t1.x += acc[q][1].x; t1.y += acc[q][1].y;
                    t1.z += acc[q][1].z; t1.w += acc[q][1].w;
                    g4[2 * lane] = t0;
                    g4[2 * lane + 1] = t1;
                }
            }
        }
        __syncthreads();

        // ---- star = att_pool weighted sum ----
        {
            float S = 0.f;
            for (int n = 0; n < N_; n++) S += simb[n];
            float inv = 1.f / (S + 1e-24f);
            float s = 0.f;
            for (int n = 0; n < N_; n++) s = fmaf(simb[n], h[n * D_ + tid], s);
            __syncthreads();          // everyone done reading old star
            star[tid] = s * inv;
        }
        __syncthreads();
    }

    // ---- outputs: star ----
    ostar[b * D_ + tid] = star[tid];

    // regather h0 into hN (h holds final hidden hL)
    for (int idx = tid; idx < N_ * D_; idx += 256) {
        int n = idx >> 8;
        hN[idx] = emb[(size_t)nid[n] * D_ + (idx & 255)];
    }
    __syncthreads();

    const int o = tid;  // output column, 0..255
    const float bA = bhn[o];
    const float bB = bhn1[o];

    // ===== gate A: out0 = g*h0 + (1-g)*hL ; out1 partial = g*h0 =====
    for (int tb = 0; tb < 2; tb++) {
        const int rbase = tb * 25;
        unsigned long long acc[25];
#pragma unroll
        for (int n = 0; n < 25; n++) acc[n] = 0ull;
        gate_seg(acc, hN, rbase, Whn + o);             // h0 vs W rows [0,256)
        gate_seg(acc, h,  rbase, Whn + D_ * D_ + o);   // hL vs W rows [256,512)
#pragma unroll
        for (int n = 0; n < 25; n++) {
            float lo, hi;
            up2(acc[n], lo, hi);
            float g = 1.f / (1.f + __expf(-(lo + hi + bA)));
            int row = rbase + n;
            float h0v = hN[row * D_ + o];
            float hLv = h[row * D_ + o];
            out0[bo + row * D_ + o] = g * h0v + (1.f - g) * hLv;
            out1[bo + row * D_ + o] = g * h0v;  // partial (alpha term)
        }
    }
    __syncthreads();

    // overwrite hL region with hg1 = hg_sum / 3
    for (int idx = tid; idx < N_ * D_; idx += 256)
        h[idx] = g_hg[bo + idx] * (1.f / 3.f);
    __syncthreads();

    // ===== gate B: out1 += (1-g1)*hg1 =====
    for (int tb = 0; tb < 2; tb++) {
        const int rbase = tb * 25;
        unsigned long long acc[25];
#pragma unroll
        for (int n = 0; n < 25; n++) acc[n] = 0ull;
        gate_seg(acc, hN, rbase, Whn1 + o);            // h0 vs W1 rows [0,256)
        gate_seg(acc, h,  rbase, Whn1 + D_ * D_ + o);  // hg1 vs W1 rows [256,512)
#pragma unroll
        for (int n = 0; n < 25; n++) {
            float lo, hi;
            up2(acc[n], lo, hi);
            float g1 = 1.f / (1.f + __expf(-(lo + hi + bB)));
            int row = rbase + n;
            float hgv = h[row * D_ + o];
            out1[bo + row * D_ + o] += (1.f - g1) * hgv;
        }
    }
}

// ---------------- launch ----------------
extern "C" void kernel_launch(void* const* d_in, const int* in_sizes, int n_in,
                              void* d_out, int out_size) {
    (void)in_sizes; (void)n_in; (void)out_size;
    const int*   inputs = (const int*)d_in[0];
    const int*   Am     = (const int*)d_in[1];
    const int*   gmask  = (const int*)d_in[2];
    /* d_in[3] = item (unused by reference) */
    const float* noise  = (const float*)d_in[4];
    const float* emb    = (const float*)d_in[5];
    const float* a0     = (const float*)d_in[6];
    const float* a1     = (const float*)d_in[7];
    const float* a2     = (const float*)d_in[8];
    const float* a3     = (const float*)d_in[9];
    const float* Whn    = (const float*)d_in[10];
    const float* bhn    = (const float*)d_in[11];
    const float* Whn1   = (const float*)d_in[12];
    const float* bhn1   = (const float*)d_in[13];

    float* out  = (float*)d_out;
    float* out0 = out;                                 // [B,N,D]
    float* ostar = out + (size_t)B_ * N_ * D_;         // [B,D]
    float* out1 = ostar + (size_t)B_ * D_;             // [B,N,D]

    cudaFuncSetAttribute(sg_kernel, cudaFuncAttributeMaxDynamicSharedMemorySize,
                         SMEM_BYTES);
    sg_kernel<<<B_, 256, SMEM_BYTES>>>(inputs, Am, gmask, noise, emb,
                                       a0, a1, a2, a3, Whn, bhn, Whn1, bhn1,
                                       out0, ostar, out1);
}

// round 11
// speedup vs baseline: 1.8059x; 1.0082x over previous
#include <cuda_runtime.h>
#include <cstdint>
#include <cstddef>

#define B_ 512
#define N_ 50
#define D_ 256
#define STEP_ 3

// shared-memory layout (float offsets)
#define SM_H      0        // [50][256] hidden
#define SM_HN     12800    // [50][256] noise slab (steps) / h0 buffer (gating)
#define SM_EM     25600    // [50][50] attention matrix
#define SM_STAR   28100    // [256]
#define SM_SIMB   28356    // [64]
#define SM_GMF    28420    // [64]
#define SM_NID    28484    // [64]
#define SM_FLOATS 28548
#define SMEM_BYTES (SM_FLOATS * 4)

// global scratch for hg accumulation (sum of step embeddings)
__device__ float g_hg[(size_t)B_ * N_ * D_];

// ---------------- helpers ----------------
__device__ __forceinline__ float wsum(float v) {
#pragma unroll
    for (int o = 16; o; o >>= 1) v += __shfl_xor_sync(0xffffffffu, v, o);
    return v;
}
__device__ __forceinline__ float sx(float v, int o) {
    return __shfl_xor_sync(0xffffffffu, v, o);
}
__device__ __forceinline__ float sgnf(float x) {
    return x > 0.f ? 1.f : (x < 0.f ? -1.f : 0.f);
}
__device__ __forceinline__ float dot4(float4 a, float4 b) {
    return a.x * b.x + a.y * b.y + a.z * b.z + a.w * b.w;
}
__device__ __forceinline__ float4 fma4(float p, float4 y, float4 a) {
    a.x = fmaf(p, y.x, a.x); a.y = fmaf(p, y.y, a.y);
    a.z = fmaf(p, y.z, a.z); a.w = fmaf(p, y.w, a.w);
    return a;
}
__device__ __forceinline__ float4 mul4(float4 a, float4 b) {
    return make_float4(a.x * b.x, a.y * b.y, a.z * b.z, a.w * b.w);
}
// packed f32x2 (FFMA2) — only reachable via PTX
__device__ __forceinline__ unsigned long long pk2(float lo, float hi) {
    unsigned long long r;
    asm("mov.b64 %0, {%1, %2};" : "=l"(r) : "f"(lo), "f"(hi));
    return r;
}
__device__ __forceinline__ void fma2(unsigned long long& d, unsigned long long a,
                                     unsigned long long b) {
    asm("fma.rn.f32x2 %0, %1, %2, %0;" : "+l"(d) : "l"(a), "l"(b));
}
__device__ __forceinline__ void up2(unsigned long long v, float& lo, float& hi) {
    asm("mov.b64 {%0, %1}, %2;" : "=f"(lo), "=f"(hi) : "l"(v));
}
__device__ __forceinline__ void cp16(uint32_t saddr, const void* gaddr) {
    asm volatile("cp.async.cg.shared.global [%0], [%1], 16;"
                 :: "r"(saddr), "l"(gaddr));
}

// per-j masked dot against register-cached ka (av is warp-uniform)
__device__ __forceinline__ float edot(int av, const float* hj, int lane,
                                      const float4 ka[4][2]) {
    const float4* y4 = (const float4*)hj;
    float4 y0 = y4[2 * lane], y1 = y4[2 * lane + 1];
    float4 c0, c1;
    switch (av) {
        case 1:  c0 = ka[0][0]; c1 = ka[0][1]; break;
        case 2:  c0 = ka[1][0]; c1 = ka[1][1]; break;
        case 3:  c0 = ka[2][0]; c1 = ka[2][1]; break;
        default: c0 = ka[3][0]; c1 = ka[3][1]; break;
    }
    return dot4(c0, y0) + dot4(c1, y1);
}

// one GEMV segment for the gating gates: acc[n] += z[n][k0..k0+3] * W[k0..k0+3][o]
__device__ __forceinline__ void gate_seg(unsigned long long acc[25],
                                         const float* zbase, int rbase,
                                         const float* __restrict__ Wcol) {
    for (int kp = 0; kp < 64; kp++) {
        const int k0 = 4 * kp;
        float w0 = __ldg(Wcol + (k0 + 0) * D_);
        float w1 = __ldg(Wcol + (k0 + 1) * D_);
        float w2 = __ldg(Wcol + (k0 + 2) * D_);
        float w3 = __ldg(Wcol + (k0 + 3) * D_);
        unsigned long long wA = pk2(w0, w1), wB = pk2(w2, w3);
#pragma unroll
        for (int n = 0; n < 25; n++) {
            const ulonglong2 z =
                *(const ulonglong2*)(zbase + (rbase + n) * D_ + k0);
            fma2(acc[n], z.x, wA);
            fma2(acc[n], z.y, wB);
        }
    }
}

// ---------------- fused kernel: one block per batch element ----------------
__global__ void __launch_bounds__(256, 2) sg_kernel(
    const int* __restrict__ inputs, const int* __restrict__ Am,
    const int* __restrict__ gmask, const float* __restrict__ noise,
    const float* __restrict__ emb,
    const float* __restrict__ a0, const float* __restrict__ a1,
    const float* __restrict__ a2, const float* __restrict__ a3,
    const float* __restrict__ Whn, const float* __restrict__ bhn,
    const float* __restrict__ Whn1, const float* __restrict__ bhn1,
    float* __restrict__ out0, float* __restrict__ ostar, float* __restrict__ out1)
{
    extern __shared__ float sm[];
    float* h    = sm + SM_H;
    float* hN   = sm + SM_HN;   // noise slab during steps, h0 in gating
    float* eM   = sm + SM_EM;
    float* star = sm + SM_STAR;
    float* simb = sm + SM_SIMB;
    float* gmF  = sm + SM_GMF;
    int*   nid  = (int*)(sm + SM_NID);

    const int b = blockIdx.x;
    const int tid = threadIdx.x;
    const int lane = tid & 31;
    const int w = tid >> 5;
    const size_t bo = (size_t)b * N_ * D_;

    // ---- indices / mask ----
    if (tid < N_) {
        nid[tid] = inputs[b * N_ + tid];
        gmF[tid] = (float)gmask[b * N_ + tid];
    }
    __syncthreads();

    // ---- gather h0 ----
    for (int idx = tid; idx < N_ * D_; idx += 256) {
        int n = idx >> 8;
        h[idx] = emb[(size_t)nid[n] * D_ + (idx & 255)];
    }
    __syncthreads();

    // ---- initial star = ave_pool(h0, gm) ----
    {
        float s = 0.f, len = 0.f;
        for (int n = 0; n < N_; n++) {
            float g = gmF[n];
            s = fmaf(h[n * D_ + tid], g, s);
            len += g;
        }
        star[tid] = s / len;
    }
    __syncthreads();

    const uint32_t hN_s = (uint32_t)__cvta_generic_to_shared(hN);

    // ================= STEP loop =================
    for (int st = 0; st < STEP_; st++) {
        // ---- prefetch this step's noise slab into hN (overlaps e+agg) ----
        {
            const float* gsrc = noise + ((size_t)st * B_ + b) * N_ * D_;
            for (int c = tid; c < N_ * D_ / 4; c += 256)
                cp16(hN_s + c * 16, gsrc + c * 4);
            asm volatile("cp.async.commit_group;" ::: "memory");
        }

        // ---- e-scores + row softmax: one warp per row i ----
        for (int i = w; i < N_; i += 8) {
            const float4* hi4 = (const float4*)(h + i * D_);
            float4 x0 = hi4[2 * lane], x1 = hi4[2 * lane + 1];
            float4 ka[4][2];
            ka[0][0] = mul4(x0, __ldg((const float4*)a0 + 2 * lane));
            ka[0][1] = mul4(x1, __ldg((const float4*)a0 + 2 * lane + 1));
            ka[1][0] = mul4(x0, __ldg((const float4*)a1 + 2 * lane));
            ka[1][1] = mul4(x1, __ldg((const float4*)a1 + 2 * lane + 1));
            ka[2][0] = mul4(x0, __ldg((const float4*)a2 + 2 * lane));
            ka[2][1] = mul4(x1, __ldg((const float4*)a2 + 2 * lane + 1));
            ka[3][0] = mul4(x0, __ldg((const float4*)a3 + 2 * lane));
            ka[3][1] = mul4(x1, __ldg((const float4*)a3 + 2 * lane + 1));

            const int* Arow = Am + (size_t)b * N_ * N_ + i * N_;
            float* er = eM + i * N_;

            // 6 groups of 8 j's; merged 16-SHFL reduction per group
            for (int jb = 0; jb < 48; jb += 8) {
                const int2 a01 = *(const int2*)(Arow + jb);
                const int2 a23 = *(const int2*)(Arow + jb + 2);
                const int2 a45 = *(const int2*)(Arow + jb + 4);
                const int2 a67 = *(const int2*)(Arow + jb + 6);
                const float* hb = h + jb * D_;
                float p0 = 0.f, p1 = 0.f, p2 = 0.f, p3 = 0.f;
                float p4 = 0.f, p5 = 0.f, p6 = 0.f, p7 = 0.f;
                if (a01.x) p0 = edot(a01.x, hb,          lane, ka);
                if (a01.y) p1 = edot(a01.y, hb + D_,     lane, ka);
                if (a23.x) p2 = edot(a23.x, hb + 2 * D_, lane, ka);
                if (a23.y) p3 = edot(a23.y, hb + 3 * D_, lane, ka);
                if (a45.x) p4 = edot(a45.x, hb + 4 * D_, lane, ka);
                if (a45.y) p5 = edot(a45.y, hb + 5 * D_, lane, ka);
                if (a67.x) p6 = edot(a67.x, hb + 6 * D_, lane, ka);
                if (a67.y) p7 = edot(a67.y, hb + 7 * D_, lane, ka);
                // merged 8-value reduction: 16 SHFL total
                p0 += sx(p0, 16); p1 += sx(p1, 16); p2 += sx(p2, 16); p3 += sx(p3, 16);
                p4 += sx(p4, 16); p5 += sx(p5, 16); p6 += sx(p6, 16); p7 += sx(p7, 16);
                float m0 = (lane & 16) ? p1 : p0;
                float m1 = (lane & 16) ? p3 : p2;
                float m2 = (lane & 16) ? p5 : p4;
                float m3 = (lane & 16) ? p7 : p6;
                m0 += sx(m0, 8); m1 += sx(m1, 8); m2 += sx(m2, 8); m3 += sx(m3, 8);
                float n0 = (lane & 8) ? m1 : m0;
                float n1 = (lane & 8) ? m3 : m2;
                n0 += sx(n0, 4); n1 += sx(n1, 4);
                float r = (lane & 4) ? n1 : n0;
                r += sx(r, 2); r += sx(r, 1);
                // lane 4g holds sum of pair k = bitrev3(g)
                if ((lane & 3) == 0) {
                    const int g = lane >> 2;
                    const int k = ((g & 1) << 2) | (g & 2) | (g >> 2);
                    int avv;
                    switch (k) {
                        case 0:  avv = a01.x; break;
                        case 1:  avv = a01.y; break;
                        case 2:  avv = a23.x; break;
                        case 3:  avv = a23.y; break;
                        case 4:  avv = a45.x; break;
                        case 5:  avv = a45.y; break;
                        case 6:  avv = a67.x; break;
                        default: avv = a67.y; break;
                    }
                    er[jb + k] = avv ? (r > 0.f ? r : 0.2f * r) : -9e15f;
                }
            }
            {   // tail j = 48, 49
                const int2 av = *(const int2*)(Arow + 48);
                float p0 = 0.f, p1 = 0.f;
                if (av.x) p0 = edot(av.x, h + 48 * D_, lane, ka);
                if (av.y) p1 = edot(av.y, h + 49 * D_, lane, ka);
#pragma unroll
                for (int o = 16; o; o >>= 1) {
                    p0 += sx(p0, o);
                    p1 += sx(p1, o);
                }
                if (lane == 0) {
                    er[48] = av.x ? (p0 > 0.f ? p0 : 0.2f * p0) : -9e15f;
                    er[49] = av.y ? (p1 > 0.f ? p1 : 0.2f * p1) : -9e15f;
                }
            }
            __syncwarp();
            // in-place row softmax
            {
                float e1 = er[lane];
                float e2 = (lane < 18) ? er[32 + lane] : -3.0e38f;
                float m = fmaxf(e1, e2);
#pragma unroll
                for (int o = 16; o; o >>= 1)
                    m = fmaxf(m, __shfl_xor_sync(0xffffffffu, m, o));
                float q1 = __expf(e1 - m);
                float q2 = (lane < 18) ? __expf(e2 - m) : 0.f;
                float S = wsum(q1 + q2);
                float inv = 1.f / S;
                er[lane] = q1 * inv;
                if (lane < 18) er[32 + lane] = q2 * inv;
            }
        }
        __syncthreads();

        // ---- aggregation into registers: rows r = w + 8q, j unrolled x2 ----
        float4 acc[7][2];
#pragma unroll
        for (int q = 0; q < 7; q++) {
            acc[q][0] = make_float4(0, 0, 0, 0);
            acc[q][1] = make_float4(0, 0, 0, 0);
        }
        {
            const float* e0 = eM + (w + 0) * N_;
            const float* e1 = eM + (w + 8) * N_;
            const float* e2 = eM + (w + 16) * N_;
            const float* e3 = eM + (w + 24) * N_;
            const float* e4 = eM + (w + 32) * N_;
            const float* e5 = eM + (w + 40) * N_;
            const float* e6 = (w + 48 < N_) ? eM + (w + 48) * N_ : e0;
            const bool has6 = (w + 48 < N_);
            for (int j = 0; j < N_; j += 2) {
                const float4* ya = (const float4*)(h + j * D_);
                const float4* yb = (const float4*)(h + (j + 1) * D_);
                float4 ya0 = ya[2 * lane], ya1 = ya[2 * lane + 1];
                float4 yb0 = yb[2 * lane], yb1 = yb[2 * lane + 1];
                float2 pe;
                pe = *(const float2*)(e0 + j);
                acc[0][0] = fma4(pe.x, ya0, acc[0][0]); acc[0][1] = fma4(pe.x, ya1, acc[0][1]);
                acc[0][0] = fma4(pe.y, yb0, acc[0][0]); acc[0][1] = fma4(pe.y, yb1, acc[0][1]);
                pe = *(const float2*)(e1 + j);
                acc[1][0] = fma4(pe.x, ya0, acc[1][0]); acc[1][1] = fma4(pe.x, ya1, acc[1][1]);
                acc[1][0] = fma4(pe.y, yb0, acc[1][0]); acc[1][1] = fma4(pe.y, yb1, acc[1][1]);
                pe = *(const float2*)(e2 + j);
                acc[2][0] = fma4(pe.x, ya0, acc[2][0]); acc[2][1] = fma4(pe.x, ya1, acc[2][1]);
                acc[2][0] = fma4(pe.y, yb0, acc[2][0]); acc[2][1] = fma4(pe.y, yb1, acc[2][1]);
                pe = *(const float2*)(e3 + j);
                acc[3][0] = fma4(pe.x, ya0, acc[3][0]); acc[3][1] = fma4(pe.x, ya1, acc[3][1]);
                acc[3][0] = fma4(pe.y, yb0, acc[3][0]); acc[3][1] = fma4(pe.y, yb1, acc[3][1]);
                pe = *(const float2*)(e4 + j);
                acc[4][0] = fma4(pe.x, ya0, acc[4][0]); acc[4][1] = fma4(pe.x, ya1, acc[4][1]);
                acc[4][0] = fma4(pe.y, yb0, acc[4][0]); acc[4][1] = fma4(pe.y, yb1, acc[4][1]);
                pe = *(const float2*)(e5 + j);
                acc[5][0] = fma4(pe.x, ya0, acc[5][0]); acc[5][1] = fma4(pe.x, ya1, acc[5][1]);
                acc[5][0] = fma4(pe.y, yb0, acc[5][0]); acc[5][1] = fma4(pe.y, yb1, acc[5][1]);
                if (has6) {
                    pe = *(const float2*)(e6 + j);
                    acc[6][0] = fma4(pe.x, ya0, acc[6][0]); acc[6][1] = fma4(pe.x, ya1, acc[6][1]);
                    acc[6][0] = fma4(pe.y, yb0, acc[6][0]); acc[6][1] = fma4(pe.y, yb1, acc[6][1]);
                }
            }
        }

        // noise slab must be in SMEM now; also fences agg h-reads before h writes
        asm volatile("cp.async.wait_group 0;" ::: "memory");
        __syncthreads();

        // star cached in registers (old star)
        const float4* s4 = (const float4*)star;
        float4 s0 = s4[2 * lane], s1 = s4[2 * lane + 1];

        // ---- stage A: sim + noise-norm reductions, q-pairs interleaved ----
        float alpha[7], nscale[7];
#pragma unroll
        for (int q0 = 0; q0 < 7; q0 += 2) {
            const int r0 = w + 8 * q0;
            const int r1 = r0 + 8;
            const bool v0 = (r0 < N_);
            const bool v1 = (q0 + 1 < 7) && (r1 < N_);
            float pa = 0.f, pb = 0.f, pc = 0.f, pd = 0.f;
            if (v0) {
                pa = dot4(acc[q0][0], s0) + dot4(acc[q0][1], s1);
                const float4* m4 = (const float4*)(hN + r0 * D_);
                float4 m0 = m4[2 * lane], m1 = m4[2 * lane + 1];
                pb = dot4(m0, m0) + dot4(m1, m1);
            }
            if (v1) {
                pc = dot4(acc[q0 + 1][0], s0) + dot4(acc[q0 + 1][1], s1);
                const float4* m4 = (const float4*)(hN + r1 * D_);
                float4 m0 = m4[2 * lane], m1 = m4[2 * lane + 1];
                pd = dot4(m0, m0) + dot4(m1, m1);
            }
#pragma unroll
            for (int o = 16; o; o >>= 1) {
                pa += sx(pa, o);
                pb += sx(pb, o);
                pc += sx(pc, o);
                pd += sx(pd, o);
            }
            alpha[q0]  = 1.f / (1.f + __expf(-pa * 0.0625f));
            nscale[q0] = 0.4f / fmaxf(sqrtf(pb), 1e-12f);
            if (q0 + 1 < 7) {
                alpha[q0 + 1]  = 1.f / (1.f + __expf(-pc * 0.0625f));
                nscale[q0 + 1] = 0.4f / fmaxf(sqrtf(pd), 1e-12f);
            }
        }

        // ---- stage B: mix + signed noise (no reductions) ----
        float pd1[7];
#pragma unroll
        for (int q = 0; q < 7; q++) {
            const int r = w + 8 * q;
            pd1[q] = 0.f;
            if (r < N_) {
                const float al = alpha[q], om = 1.f - al, sc = nscale[q];
                const float4* m4 = (const float4*)(hN + r * D_);
                float4 n0 = m4[2 * lane], n1 = m4[2 * lane + 1];
                float4 v0, v1;
                v0.x = om * acc[q][0].x + al * s0.x;
                v0.y = om * acc[q][0].y + al * s0.y;
                v0.z = om * acc[q][0].z + al * s0.z;
                v0.w = om * acc[q][0].w + al * s0.w;
                v1.x = om * acc[q][1].x + al * s1.x;
                v1.y = om * acc[q][1].y + al * s1.y;
                v1.z = om * acc[q][1].z + al * s1.z;
                v1.w = om * acc[q][1].w + al * s1.w;
                v0.x = fmaf(sgnf(v0.x) * sc, n0.x, v0.x);
                v0.y = fmaf(sgnf(v0.y) * sc, n0.y, v0.y);
                v0.z = fmaf(sgnf(v0.z) * sc, n0.z, v0.z);
                v0.w = fmaf(sgnf(v0.w) * sc, n0.w, v0.w);
                v1.x = fmaf(sgnf(v1.x) * sc, n1.x, v1.x);
                v1.y = fmaf(sgnf(v1.y) * sc, n1.y, v1.y);
                v1.z = fmaf(sgnf(v1.z) * sc, n1.z, v1.z);
                v1.w = fmaf(sgnf(v1.w) * sc, n1.w, v1.w);
                acc[q][0] = v0;
                acc[q][1] = v1;
                pd1[q] = dot4(v0, s0) + dot4(v1, s1);  // att_pool numerator
            }
        }

        // ---- stage C: all 7 d1 chains in one interleaved butterfly ----
#pragma unroll
        for (int o = 16; o; o >>= 1) {
#pragma unroll
            for (int q = 0; q < 7; q++)
                pd1[q] += sx(pd1[q], o);
        }
        if (lane == 0) {
#pragma unroll
            for (int q = 0; q < 7; q++) {
                const int r = w + 8 * q;
                if (r < N_) simb[r] = __expf(pd1[q]) * gmF[r];
            }
        }

        // ---- write new h + accumulate hg ----
#pragma unroll
        for (int q = 0; q < 7; q++) {
            const int r = w + 8 * q;
            if (r < N_) {
                float4* h4 = (float4*)(h + r * D_);
                h4[2 * lane] = acc[q][0];
                h4[2 * lane + 1] = acc[q][1];
                float4* g4 = (float4*)(g_hg + bo + (size_t)r * D_);
                if (st == 0) {
                    g4[2 * lane] = acc[q][0];
                    g4[2 * lane + 1] = acc[q][1];
                } else {
                    float4 t0 = g4[2 * lane], t1 = g4[2 * lane + 1];
                    t0.x += acc[q][0].x; t0.y += acc[q][0].y;
                    t0.z += acc[q][0].z; t0.w += acc[q][0].w;
                    t1.x += acc[q][1].x; t1.y += acc[q][1].y;
                    t1.z += acc[q][1].z; t1.w += acc[q][1].w;
                    g4[2 * lane] = t0;
                    g4[2 * lane + 1] = t1;
                }
            }
        }
        __syncthreads();

        // ---- star = att_pool weighted sum ----
        {
            float S = 0.f;
            for (int n = 0; n < N_; n++) S += simb[n];
            float inv = 1.f / (S + 1e-24f);
            float s = 0.f;
            for (int n = 0; n < N_; n++) s = fmaf(simb[n], h[n * D_ + tid], s);
            __syncthreads();          // everyone done reading old star
            star[tid] = s * inv;
        }
        __syncthreads();
    }

    // ---- outputs: star ----
    ostar[b * D_ + tid] = star[tid];

    // regather h0 into hN (h holds final hidden hL)
    for (int idx = tid; idx < N_ * D_; idx += 256) {
        int n = idx >> 8;
        hN[idx] = emb[(size_t)nid[n] * D_ + (idx & 255)];
    }
    __syncthreads();

    const int o = tid;  // output column, 0..255
    const float bA = bhn[o];
    const float bB = bhn1[o];

    // ===== gate A: out0 = g*h0 + (1-g)*hL ; out1 partial = g*h0 =====
    for (int tb = 0; tb < 2; tb++) {
        const int rbase = tb * 25;
        unsigned long long acc[25];
#pragma unroll
        for (int n = 0; n < 25; n++) acc[n] = 0ull;
        gate_seg(acc, hN, rbase, Whn + o);             // h0 vs W rows [0,256)
        gate_seg(acc, h,  rbase, Whn + D_ * D_ + o);   // hL vs W rows [256,512)
#pragma unroll
        for (int n = 0; n < 25; n++) {
            float lo, hi;
            up2(acc[n], lo, hi);
            float g = 1.f / (1.f + __expf(-(lo + hi + bA)));
            int row = rbase + n;
            float h0v = hN[row * D_ + o];
            float hLv = h[row * D_ + o];
            out0[bo + row * D_ + o] = g * h0v + (1.f - g) * hLv;
            out1[bo + row * D_ + o] = g * h0v;  // partial (alpha term)
        }
    }
    __syncthreads();

    // overwrite hL region with hg1 = hg_sum / 3
    for (int idx = tid; idx < N_ * D_; idx += 256)
        h[idx] = g_hg[bo + idx] * (1.f / 3.f);
    __syncthreads();

    // ===== gate B: out1 += (1-g1)*hg1 =====
    for (int tb = 0; tb < 2; tb++) {
        const int rbase = tb * 25;
        unsigned long long acc[25];
#pragma unroll
        for (int n = 0; n < 25; n++) acc[n] = 0ull;
        gate_seg(acc, hN, rbase, Whn1 + o);            // h0 vs W1 rows [0,256)
        gate_seg(acc, h,  rbase, Whn1 + D_ * D_ + o);  // hg1 vs W1 rows [256,512)
#pragma unroll
        for (int n = 0; n < 25; n++) {
            float lo, hi;
            up2(acc[n], lo, hi);
            float g1 = 1.f / (1.f + __expf(-(lo + hi + bB)));
            int row = rbase + n;
            float hgv = h[row * D_ + o];
            out1[bo + row * D_ + o] += (1.f - g1) * hgv;
        }
    }
}

// ---------------- launch ----------------
extern "C" void kernel_launch(void* const* d_in, const int* in_sizes, int n_in,
                              void* d_out, int out_size) {
    (void)in_sizes; (void)n_in; (void)out_size;
    const int*   inputs = (const int*)d_in[0];
    const int*   Am     = (const int*)d_in[1];
    const int*   gmask  = (const int*)d_in[2];
    /* d_in[3] = item (unused by reference) */
    const float* noise  = (const float*)d_in[4];
    const float* emb    = (const float*)d_in[5];
    const float* a0     = (const float*)d_in[6];
    const float* a1     = (const float*)d_in[7];
    const float* a2     = (const float*)d_in[8];
    const float* a3     = (const float*)d_in[9];
    const float* Whn    = (const float*)d_in[10];
    const float* bhn    = (const float*)d_in[11];
    const float* Whn1   = (const float*)d_in[12];
    const float* bhn1   = (const float*)d_in[13];

    float* out  = (float*)d_out;
    float* out0 = out;                                 // [B,N,D]
    float* ostar = out + (size_t)B_ * N_ * D_;         // [B,D]
    float* out1 = ostar + (size_t)B_ * D_;             // [B,N,D]

    cudaFuncSetAttribute(sg_kernel, cudaFuncAttributeMaxDynamicSharedMemorySize,
                         SMEM_BYTES);
    sg_kernel<<<B_, 256, SMEM_BYTES>>>(inputs, Am, gmask, noise, emb,
                                       a0, a1, a2, a3, Whn, bhn, Whn1, bhn1,
                                       out0, ostar, out1);
}